// round 3
// baseline (speedup 1.0000x reference)
#include <cuda_runtime.h>
#include <math.h>

#define TT 64
#define BB 256
#define EMBD 1024
#define ADIM 6
#define STOCHD 64
#define HIDD 512
#define FEATD 512
#define STATED 576
#define TBD (TT*BB)
#define LOG2PI_F 1.837877066409345483560659472811f

// ------------------------- static device scratch -------------------------
__device__ float g_states[TBD*STATED];        // [h(512) | s(64)] per row
__device__ float g_qmu[TBD*STOCHD];
__device__ float g_qstd[TBD*STOCHD];
__device__ float g_carryA[BB*STATED];         // carry ping-pong: [s(64) | h(512)]
__device__ float g_carryB[BB*STATED];
__device__ float g_zeroc[BB*STATED];          // zero, never written
__device__ float g_rz[BB*1024];
__device__ float g_y1[BB*FEATD];
__device__ float g_y2[BB*FEATD];
__device__ float g_Wrz[1024*STATED];          // packed [Wih_s | Whh] for r,z gates
__device__ float g_P[TBD*1536];               // action+bias gate precompute
__device__ float g_PE[TBD*FEATD];             // emb_prev @ W0_e + b0
__device__ float g_E[TBD*EMBD];               // ep_mlp(states) = emb_mu (and shifted = pre_emb)
__device__ float g_pcat[TBD*1536];            // [h | pre_emb]
__device__ float g_praw[TBD*2*STOCHD];
__device__ float g_big1[TBD*FEATD];
__device__ float g_big2[TBD*FEATD];
__device__ float g_e0l1[FEATD];
__device__ float g_e0[EMBD];
__device__ double g_acc[3];

// ------------------------- math helpers -------------------------
__device__ __forceinline__ float softplusf(float x) {
    return fmaxf(x, 0.f) + log1pf(expf(-fabsf(x)));
}
__device__ __forceinline__ float sigmoidf_(float x) { return 1.f / (1.f + expf(-x)); }
__device__ __forceinline__ float eluf(float x) { return x > 0.f ? x : expm1f(x); }
template<int ACTF>
__device__ __forceinline__ float actf(float v) {
    if (ACTF == 1) return eluf(v);
    if (ACTF == 2) return sigmoidf_(v);
    return v;
}

// ------------------------- packed f32x2 helpers -------------------------
typedef unsigned long long u64;
__device__ __forceinline__ void ffma2(u64& d, u64 a, u64 b) {
    asm("fma.rn.f32x2 %0, %1, %2, %0;" : "+l"(d) : "l"(a), "l"(b));
}
__device__ __forceinline__ u64 pdup(float x) {
    u64 r; unsigned xi = __float_as_uint(x);
    asm("mov.b64 %0, {%1, %2};" : "=l"(r) : "r"(xi), "r"(xi));
    return r;
}
__device__ __forceinline__ float2 unpk(u64 v) {
    unsigned lo, hi;
    asm("mov.b64 {%0, %1}, %2;" : "=r"(lo), "=r"(hi) : "l"(v));
    return make_float2(__uint_as_float(lo), __uint_as_float(hi));
}

// ------------------------- prep kernels -------------------------
__global__ void prep_wrz(const float* __restrict__ Wih, const float* __restrict__ Whh,
                         float* __restrict__ Wrz)
{
    int idx = blockIdx.x * blockDim.x + threadIdx.x;
    if (idx >= 1024 * STATED) return;
    int j = idx / STATED, k = idx % STATED;
    Wrz[idx] = (k < 64) ? Wih[j * 70 + k] : Whh[j * 512 + (k - 64)];
}

// P[r,j] = action[r]·Wih[j,64:70] + bih[j] + (j<1024 ? bhh[j] : 0)
__global__ void prep_P(const float* __restrict__ action, const float* __restrict__ Wih,
                       const float* __restrict__ bih, const float* __restrict__ bhh,
                       float* __restrict__ P)
{
    int r = blockIdx.x;
    __shared__ float a[ADIM];
    if (threadIdx.x < ADIM) a[threadIdx.x] = action[(size_t)r * ADIM + threadIdx.x];
    __syncthreads();
    for (int j = threadIdx.x; j < 1536; j += 256) {
        float v = bih[j];
#pragma unroll
        for (int k = 0; k < ADIM; k++) v = fmaf(a[k], Wih[j * 70 + 64 + k], v);
        if (j < 1024) v += bhh[j];
        P[(size_t)r * 1536 + j] = v;
    }
}

// ------------------------- big batched GEMM (128x128 tile, f32x2) -------------------------
// C[M=16384, N] = act(A@W^T + bias). N%128==0, K%16==0. rowShift: A row r>=256 -> r-256.
template<int ACT>
__global__ __launch_bounds__(256) void gemm_big(
    const float* __restrict__ A, int ldA,
    const float* __restrict__ W, int ldW,
    const float* __restrict__ bias,
    float* __restrict__ C, int ldC,
    int K, int rowShift)
{
    __shared__ __align__(16) u64 As2[16][129];
    __shared__ __align__(16) float Ws[16][130];
    int tid = threadIdx.x, tx = tid & 15, ty = tid >> 4;
    int row0 = blockIdx.y * 128, col0 = blockIdx.x * 128;
    u64 acc[8][4];
#pragma unroll
    for (int i = 0; i < 8; i++)
#pragma unroll
        for (int p = 0; p < 4; p++) acc[i][p] = 0ULL;

    for (int k0 = 0; k0 < K; k0 += 16) {
#pragma unroll
        for (int i = 0; i < 8; i++) {
            int e = tid + i * 256;
            int kk = e & 15, m = e >> 4;
            int gm = row0 + m;
            if (rowShift && gm >= 256) gm -= 256;
            As2[kk][m] = pdup(A[(size_t)gm * ldA + k0 + kk]);
            Ws[kk][m] = W[(size_t)(col0 + m) * ldW + k0 + kk];
        }
        __syncthreads();
#pragma unroll
        for (int kk = 0; kk < 16; kk++) {
            u64 b[4];
#pragma unroll
            for (int p = 0; p < 4; p++)
                b[p] = *reinterpret_cast<const u64*>(&Ws[kk][tx * 8 + 2 * p]);
#pragma unroll
            for (int i = 0; i < 8; i++) {
                u64 a = As2[kk][ty * 8 + i];
#pragma unroll
                for (int p = 0; p < 4; p++) ffma2(acc[i][p], a, b[p]);
            }
        }
        __syncthreads();
    }
#pragma unroll
    for (int i = 0; i < 8; i++) {
        int gm = row0 + ty * 8 + i;
#pragma unroll
        for (int p = 0; p < 4; p++) {
            int col = col0 + tx * 8 + 2 * p;
            float2 v = unpk(acc[i][p]);
            C[(size_t)gm * ldC + col]     = actf<ACT>(v.x + bias[col]);
            C[(size_t)gm * ldC + col + 1] = actf<ACT>(v.y + bias[col + 1]);
        }
    }
}

// ------------------------- per-step GEMM (32x64 tile, f32x2) -------------------------
// C = act(A@W^T + Add), M=256, grid=(N/64, 8). ldAdd=0 -> bias broadcast.
template<int ACT>
__global__ __launch_bounds__(256) void step_gemm(
    const float* __restrict__ A, int ldA,
    const float* __restrict__ W, int ldW,
    const float* __restrict__ Add, int ldAdd,
    float* __restrict__ C, int ldC, int K)
{
    __shared__ __align__(16) u64 As2[16][33];
    __shared__ __align__(16) float Ws[16][66];
    int tid = threadIdx.x, tx = tid & 15, ty = tid >> 4;
    int row0 = blockIdx.y * 32, col0 = blockIdx.x * 64;
    u64 acc[2][2];
    acc[0][0] = acc[0][1] = acc[1][0] = acc[1][1] = 0ULL;

    for (int k0 = 0; k0 < K; k0 += 16) {
#pragma unroll
        for (int i = 0; i < 2; i++) {
            int e = tid + i * 256;
            int kk = e & 15, m = e >> 4;
            As2[kk][m] = pdup(A[(size_t)(row0 + m) * ldA + k0 + kk]);
        }
#pragma unroll
        for (int i = 0; i < 4; i++) {
            int e = tid + i * 256;
            int kk = e & 15, n = e >> 4;
            Ws[kk][n] = W[(size_t)(col0 + n) * ldW + k0 + kk];
        }
        __syncthreads();
#pragma unroll
        for (int kk = 0; kk < 16; kk++) {
            u64 a0 = As2[kk][ty * 2], a1 = As2[kk][ty * 2 + 1];
            u64 b0 = *reinterpret_cast<const u64*>(&Ws[kk][tx * 4]);
            u64 b1 = *reinterpret_cast<const u64*>(&Ws[kk][tx * 4 + 2]);
            ffma2(acc[0][0], a0, b0); ffma2(acc[0][1], a0, b1);
            ffma2(acc[1][0], a1, b0); ffma2(acc[1][1], a1, b1);
        }
        __syncthreads();
    }
#pragma unroll
    for (int i = 0; i < 2; i++) {
        int gm = row0 + ty * 2 + i;
#pragma unroll
        for (int p = 0; p < 2; p++) {
            int col = col0 + tx * 4 + 2 * p;
            float2 v = unpk(acc[i][p]);
            float a0 = Add[(size_t)gm * ldAdd + col];
            float a1 = Add[(size_t)gm * ldAdd + col + 1];
            C[(size_t)gm * ldC + col]     = actf<ACT>(v.x + a0);
            C[(size_t)gm * ldC + col + 1] = actf<ACT>(v.y + a1);
        }
    }
}

// ------------------------- step: n-gate + h update -------------------------
// accI = s @ Wih_n_s (K=64); accH = h @ Whh_n (K=512).
// n = tanh(inn + r*hn); h' = (1-z)n + z h.
__global__ __launch_bounds__(256) void step_nh(
    const float* __restrict__ cin, const float* __restrict__ rz,
    const float* __restrict__ Wih, const float* __restrict__ Whh,
    const float* __restrict__ bhh, const float* __restrict__ P_t,
    float* __restrict__ cout, float* __restrict__ states_t)
{
    __shared__ __align__(16) u64 As2[16][33];
    __shared__ __align__(16) float Ws[16][66];
    int tid = threadIdx.x, tx = tid & 15, ty = tid >> 4;
    int row0 = blockIdx.y * 32, col0 = blockIdx.x * 64;
    u64 accI[2][2], accH[2][2];
    accI[0][0]=accI[0][1]=accI[1][0]=accI[1][1]=0ULL;
    accH[0][0]=accH[0][1]=accH[1][0]=accH[1][1]=0ULL;

    for (int k0 = 0; k0 < STATED; k0 += 16) {
#pragma unroll
        for (int i = 0; i < 2; i++) {
            int e = tid + i * 256;
            int kk = e & 15, m = e >> 4;
            As2[kk][m] = pdup(cin[(size_t)(row0 + m) * STATED + k0 + kk]);
        }
        if (k0 < 64) {
#pragma unroll
            for (int i = 0; i < 4; i++) {
                int e = tid + i * 256;
                int kk = e & 15, n = e >> 4;
                Ws[kk][n] = Wih[(size_t)(1024 + col0 + n) * 70 + k0 + kk];
            }
        } else {
#pragma unroll
            for (int i = 0; i < 4; i++) {
                int e = tid + i * 256;
                int kk = e & 15, n = e >> 4;
                Ws[kk][n] = Whh[(size_t)(1024 + col0 + n) * 512 + (k0 - 64) + kk];
            }
        }
        __syncthreads();
        if (k0 < 64) {
#pragma unroll
            for (int kk = 0; kk < 16; kk++) {
                u64 a0 = As2[kk][ty * 2], a1 = As2[kk][ty * 2 + 1];
                u64 b0 = *reinterpret_cast<const u64*>(&Ws[kk][tx * 4]);
                u64 b1 = *reinterpret_cast<const u64*>(&Ws[kk][tx * 4 + 2]);
                ffma2(accI[0][0], a0, b0); ffma2(accI[0][1], a0, b1);
                ffma2(accI[1][0], a1, b0); ffma2(accI[1][1], a1, b1);
            }
        } else {
#pragma unroll
            for (int kk = 0; kk < 16; kk++) {
                u64 a0 = As2[kk][ty * 2], a1 = As2[kk][ty * 2 + 1];
                u64 b0 = *reinterpret_cast<const u64*>(&Ws[kk][tx * 4]);
                u64 b1 = *reinterpret_cast<const u64*>(&Ws[kk][tx * 4 + 2]);
                ffma2(accH[0][0], a0, b0); ffma2(accH[0][1], a0, b1);
                ffma2(accH[1][0], a1, b0); ffma2(accH[1][1], a1, b1);
            }
        }
        __syncthreads();
    }
#pragma unroll
    for (int i = 0; i < 2; i++) {
        int gm = row0 + ty * 2 + i;
#pragma unroll
        for (int p = 0; p < 2; p++) {
            float2 vI = unpk(accI[i][p]);
            float2 vH = unpk(accH[i][p]);
#pragma unroll
            for (int half = 0; half < 2; half++) {
                int c = col0 + tx * 4 + 2 * p + half;
                float inn = (half ? vI.y : vI.x) + P_t[(size_t)gm * 1536 + 1024 + c];
                float hn  = (half ? vH.y : vH.x) + bhh[1024 + c];
                float r = rz[(size_t)gm * 1024 + c];
                float z = rz[(size_t)gm * 1024 + 512 + c];
                float n = tanhf(inn + r * hn);
                float hp = cin[(size_t)gm * STATED + 64 + c];
                float h = (1.f - z) * n + z * hp;
                cout[(size_t)gm * STATED + 64 + c] = h;
                states_t[(size_t)gm * STATED + c] = h;
            }
        }
    }
}

// ------------------------- step: L2 head + sample -------------------------
// qraw[256,128] = y2@W2^T + b2; mu=cols0..63, std=softplus(cols64..127)+1e-4; s=mu+std*eps.
__global__ __launch_bounds__(256) void step_l2s(
    const float* __restrict__ y2, const float* __restrict__ W2, const float* __restrict__ b2,
    const float* __restrict__ eps_t, float* __restrict__ qmu_t, float* __restrict__ qstd_t,
    float* __restrict__ cout, float* __restrict__ states_t)
{
    __shared__ __align__(16) u64 As2[16][9];
    __shared__ __align__(16) float Ws[16][130];
    __shared__ float qsm[8][128];
    int tid = threadIdx.x, tx = tid & 31, ty = tid >> 5;
    int row0 = blockIdx.x * 8;
    u64 acc0 = 0ULL, acc1 = 0ULL;

    for (int k0 = 0; k0 < 512; k0 += 16) {
        if (tid < 128) {
            int kk = tid & 15, m = tid >> 4;
            As2[kk][m] = pdup(y2[(size_t)(row0 + m) * 512 + k0 + kk]);
        }
#pragma unroll
        for (int i = 0; i < 8; i++) {
            int e = tid + i * 256;
            int kk = e & 15, n = e >> 4;
            Ws[kk][n] = W2[(size_t)n * 512 + k0 + kk];
        }
        __syncthreads();
#pragma unroll
        for (int kk = 0; kk < 16; kk++) {
            u64 a = As2[kk][ty];
            u64 b0 = *reinterpret_cast<const u64*>(&Ws[kk][tx * 4]);
            u64 b1 = *reinterpret_cast<const u64*>(&Ws[kk][tx * 4 + 2]);
            ffma2(acc0, a, b0); ffma2(acc1, a, b1);
        }
        __syncthreads();
    }
    {
        float2 v0 = unpk(acc0), v1 = unpk(acc1);
        int c = tx * 4;
        qsm[ty][c]     = v0.x + b2[c];
        qsm[ty][c + 1] = v0.y + b2[c + 1];
        qsm[ty][c + 2] = v1.x + b2[c + 2];
        qsm[ty][c + 3] = v1.y + b2[c + 3];
    }
    __syncthreads();
    for (int e = tid; e < 512; e += 256) {
        int rr = e >> 6, i = e & 63;
        float mu = qsm[rr][i];
        float sd = softplusf(qsm[rr][64 + i]) + 1e-4f;
        int gm = row0 + rr;
        float s = fmaf(sd, eps_t[(size_t)gm * 64 + i], mu);
        qmu_t[(size_t)gm * 64 + i] = mu;
        qstd_t[(size_t)gm * 64 + i] = sd;
        cout[(size_t)gm * STATED + i] = s;
        states_t[(size_t)gm * STATED + 512 + i] = s;
    }
}

// ------------------------- prior input / e0 -------------------------
__global__ void build_priorcat(const float* __restrict__ states, const float* __restrict__ E,
                               const float* __restrict__ e0, float* __restrict__ out)
{
    int r = blockIdx.x;
    int t = r >> 8;
    const float* src = (t == 0) ? e0 : (E + (size_t)(r - 256) * EMBD);
    float* o = out + (size_t)r * 1536;
    const float* st = states + (size_t)r * STATED;
    for (int c = threadIdx.x; c < 1536; c += 256)
        o[c] = (c < 512) ? st[c] : src[c - 512];
}

__global__ void e0_l1(const float* __restrict__ ep_b0, const float* __restrict__ ep_W1,
                      const float* __restrict__ ep_b1, float* __restrict__ l1)
{
    __shared__ float x0[512];
    for (int k = threadIdx.x; k < 512; k += 256) x0[k] = eluf(ep_b0[k]);
    __syncthreads();
    for (int o = threadIdx.x; o < 512; o += 256) {
        float v = ep_b1[o];
        for (int k = 0; k < 512; k++) v = fmaf(x0[k], ep_W1[(size_t)o * 512 + k], v);
        l1[o] = eluf(v);
    }
}

__global__ void e0_head(const float* __restrict__ l1, const float* __restrict__ ep_W2,
                        const float* __restrict__ ep_b2, float* __restrict__ e0)
{
    int o = blockIdx.x * 256 + threadIdx.x;
    float v = ep_b2[o];
    for (int k = 0; k < 512; k++) v = fmaf(l1[k], ep_W2[(size_t)o * 512 + k], v);
    e0[o] = v;
}

// ------------------------- reductions -------------------------
__global__ void zero_acc_k(double* acc) { if (threadIdx.x < 3) acc[threadIdx.x] = 0.0; }

__global__ void kl_reduce_k(const float* __restrict__ praw, const float* __restrict__ qmu,
                            const float* __restrict__ qstd, double* __restrict__ acc)
{
    __shared__ double sh[256];
    double s = 0.0;
    long total = (long)TBD * STOCHD;
    for (long idx = blockIdx.x * (long)blockDim.x + threadIdx.x; idx < total;
         idx += (long)gridDim.x * blockDim.x) {
        int r = (int)(idx >> 6), i = (int)(idx & 63);
        float pmu = praw[(size_t)r * 128 + i];
        float psd = softplusf(praw[(size_t)r * 128 + 64 + i]) + 1e-4f;
        float qm = qmu[idx], qs = qstd[idx];
        float d = qm - pmu;
        float kl = logf(psd / qs) + (qs * qs + d * d) / (2.f * psd * psd) - 0.5f;
        s += (double)kl;
    }
    sh[threadIdx.x] = s; __syncthreads();
    for (int o = 128; o > 0; o >>= 1) {
        if (threadIdx.x < o) sh[threadIdx.x] += sh[threadIdx.x + o];
        __syncthreads();
    }
    if (threadIdx.x == 0) atomicAdd(acc, sh[0]);
}

__global__ void emb_reduce_k(const float* __restrict__ emb, const float* __restrict__ embmu,
                             double* __restrict__ acc)
{
    __shared__ double sh[256];
    double s = 0.0;
    long total = (long)TBD * EMBD;
    for (long idx = blockIdx.x * (long)blockDim.x + threadIdx.x; idx < total;
         idx += (long)gridDim.x * blockDim.x) {
        float d = emb[idx] - embmu[idx];
        s += (double)(0.5f * d * d + 0.5f * LOG2PI_F);
    }
    sh[threadIdx.x] = s; __syncthreads();
    for (int o = 128; o > 0; o >>= 1) {
        if (threadIdx.x < o) sh[threadIdx.x] += sh[threadIdx.x + o];
        __syncthreads();
    }
    if (threadIdx.x == 0) atomicAdd(acc, sh[0]);
}

__global__ void reward_reduce_k(const float* __restrict__ big2, const float* __restrict__ W,
                                const float* __restrict__ bias, const float* __restrict__ reward,
                                double* __restrict__ acc)
{
    __shared__ double sh[8];
    int lane = threadIdx.x & 31;
    int wib = threadIdx.x >> 5;
    int gwarp = (blockIdx.x * blockDim.x + threadIdx.x) >> 5;
    int nwarps = (gridDim.x * blockDim.x) >> 5;
    double local = 0.0;
    for (int r = gwarp; r < TBD; r += nwarps) {
        float sum = 0.f;
        const float* row = big2 + (size_t)r * FEATD;
        for (int k = lane; k < FEATD; k += 32) sum = fmaf(row[k], W[k], sum);
#pragma unroll
        for (int o = 16; o > 0; o >>= 1) sum += __shfl_xor_sync(0xffffffffu, sum, o);
        if (lane == 0) {
            float d = reward[r] - (sum + bias[0]);
            local += (double)(0.5f * d * d + 0.5f * LOG2PI_F);
        }
    }
    if (lane == 0) sh[wib] = local;
    __syncthreads();
    if (threadIdx.x == 0) {
        double t = 0.0;
        for (int i = 0; i < 8; i++) t += sh[i];
        atomicAdd(acc, t);
    }
}

__global__ void finalize_k(const double* __restrict__ acc, float* __restrict__ out, int n) {
    double inv = 1.0 / (double)(TT * BB);
    float loss = (float)((acc[0] + acc[1] + acc[2]) * inv);
    for (int i = 0; i < n; i++) out[i] = loss;
}

// ------------------------- host -------------------------
static float* symaddr(const void* sym) {
    void* p = nullptr;
    cudaGetSymbolAddress(&p, sym);
    return (float*)p;
}

extern "C" void kernel_launch(void* const* d_in, const int* in_sizes, int n_in,
                              void* d_out, int out_size)
{
    const float* emb     = (const float*)d_in[0];
    const float* action  = (const float*)d_in[1];
    const float* reward  = (const float*)d_in[2];
    const float* eps     = (const float*)d_in[3];
    const float* gru_Wih = (const float*)d_in[4];
    const float* gru_bih = (const float*)d_in[5];
    const float* gru_Whh = (const float*)d_in[6];
    const float* gru_bhh = (const float*)d_in[7];
    const float* st_W0 = (const float*)d_in[8];  const float* st_b0 = (const float*)d_in[9];
    const float* st_W1 = (const float*)d_in[10]; const float* st_b1 = (const float*)d_in[11];
    const float* st_W2 = (const float*)d_in[12]; const float* st_b2 = (const float*)d_in[13];
    const float* ep_W0 = (const float*)d_in[14]; const float* ep_b0 = (const float*)d_in[15];
    const float* ep_W1 = (const float*)d_in[16]; const float* ep_b1 = (const float*)d_in[17];
    const float* ep_W2 = (const float*)d_in[18]; const float* ep_b2 = (const float*)d_in[19];
    const float* rp_W0 = (const float*)d_in[20]; const float* rp_b0 = (const float*)d_in[21];
    const float* rp_W1 = (const float*)d_in[22]; const float* rp_b1 = (const float*)d_in[23];
    const float* rp_W2 = (const float*)d_in[24]; const float* rp_b2 = (const float*)d_in[25];

    float* states = symaddr(g_states);
    float* qmu    = symaddr(g_qmu);
    float* qstd   = symaddr(g_qstd);
    float* carryA = symaddr(g_carryA);
    float* carryB = symaddr(g_carryB);
    float* zeroc  = symaddr(g_zeroc);
    float* rz     = symaddr(g_rz);
    float* y1     = symaddr(g_y1);
    float* y2     = symaddr(g_y2);
    float* Wrz    = symaddr(g_Wrz);
    float* P      = symaddr(g_P);
    float* PE     = symaddr(g_PE);
    float* E      = symaddr(g_E);
    float* pcat   = symaddr(g_pcat);
    float* praw   = symaddr(g_praw);
    float* big1   = symaddr(g_big1);
    float* big2   = symaddr(g_big2);
    float* e0l1   = symaddr(g_e0l1);
    float* e0     = symaddr(g_e0);
    double* acc   = (double*)symaddr(g_acc);

    zero_acc_k<<<1, 32>>>(acc);

    // ---- prep (independent of recurrence) ----
    prep_wrz<<<(1024 * STATED + 255) / 256, 256>>>(gru_Wih, gru_Whh, Wrz);
    prep_P<<<TBD, 256>>>(action, gru_Wih, gru_bih, gru_bhh, P);
    // PE = emb_prev @ st_W0[:,512:]^T + st_b0   [TBD,512], K=1024, rowShift
    gemm_big<0><<<dim3(4, 128), 256>>>(emb, EMBD, st_W0 + 512, 1536, st_b0, PE, FEATD, EMBD, 1);
    e0_l1<<<1, 256>>>(ep_b0, ep_W1, ep_b1, e0l1);
    e0_head<<<4, 256>>>(e0l1, ep_W2, ep_b2, e0);

    // ---- sequential recurrence ----
    for (int t = 0; t < TT; t++) {
        float* cin  = (t == 0) ? zeroc : ((t & 1) ? carryB : carryA);
        float* cout = ((t + 1) & 1) ? carryB : carryA;
        float* st_t = states + (size_t)t * BB * STATED;

        // r,z gates: [256,1024] = sigmoid(carry@Wrz^T + P)
        step_gemm<2><<<dim3(16, 8), 256>>>(cin, STATED, Wrz, STATED,
                                           P + (size_t)t * BB * 1536, 1536, rz, 1024, STATED);
        // n gate + h update
        step_nh<<<dim3(8, 8), 256>>>(cin, rz, gru_Wih, gru_Whh, gru_bhh,
                                     P + (size_t)t * BB * 1536, cout, st_t);
        // posterior L0: elu(h@W0_h^T + PE[t])
        step_gemm<1><<<dim3(8, 8), 256>>>(cout + 64, STATED, st_W0, 1536,
                                          PE + (size_t)t * BB * FEATD, FEATD, y1, FEATD, HIDD);
        // posterior L1
        step_gemm<1><<<dim3(8, 8), 256>>>(y1, FEATD, st_W1, FEATD, st_b1, 0, y2, FEATD, FEATD);
        // L2 + sample
        step_l2s<<<32, 256>>>(y2, st_W2, st_b2, eps + (size_t)t * BB * STOCHD,
                              qmu + (size_t)t * BB * STOCHD, qstd + (size_t)t * BB * STOCHD,
                              cout, st_t);
    }

    // ---- shared ep-MLP pass: E = ep_mlp(states) (= emb_mu; shifted = pre_emb) ----
    gemm_big<1><<<dim3(4, 128), 256>>>(states, STATED, ep_W0, STATED, ep_b0, big1, FEATD, STATED, 0);
    gemm_big<1><<<dim3(4, 128), 256>>>(big1, FEATD, ep_W1, FEATD, ep_b1, big2, FEATD, FEATD, 0);
    gemm_big<0><<<dim3(8, 128), 256>>>(big2, FEATD, ep_W2, FEATD, ep_b2, E, EMBD, FEATD, 0);

    // ---- prior path ----
    build_priorcat<<<TBD, 256>>>(states, E, e0, pcat);
    gemm_big<1><<<dim3(4, 128), 256>>>(pcat, 1536, st_W0, 1536, st_b0, big1, FEATD, 1536, 0);
    gemm_big<1><<<dim3(4, 128), 256>>>(big1, FEATD, st_W1, FEATD, st_b1, big2, FEATD, FEATD, 0);
    gemm_big<0><<<dim3(1, 128), 256>>>(big2, FEATD, st_W2, FEATD, st_b2, praw, 128, FEATD, 0);
    kl_reduce_k<<<1024, 256>>>(praw, qmu, qstd, acc + 0);

    // ---- emb loss (E already = emb_mu) ----
    emb_reduce_k<<<2048, 256>>>(emb, E, acc + 1);

    // ---- reward loss ----
    gemm_big<1><<<dim3(4, 128), 256>>>(states, STATED, rp_W0, STATED, rp_b0, big1, FEATD, STATED, 0);
    gemm_big<1><<<dim3(4, 128), 256>>>(big1, FEATD, rp_W1, FEATD, rp_b1, big2, FEATD, FEATD, 0);
    reward_reduce_k<<<512, 256>>>(big2, rp_W2, rp_b2, reward, acc + 2);

    finalize_k<<<1, 1>>>(acc, (float*)d_out, out_size);
}

// round 4
// speedup vs baseline: 1.8790x; 1.8790x over previous
#include <cuda_runtime.h>
#include <cuda_bf16.h>
#include <math.h>

#define TT 64
#define BB 256
#define EMBD 1024
#define ADIM 6
#define STOCHD 64
#define HIDD 512
#define FEATD 512
#define STATED 576
#define TBD (TT*BB)
#define LOG2PI_F 1.837877066409345483560659472811f

typedef __nv_bfloat16 bf16;

// ---------------- scratch ----------------
__device__ float g_carryA[BB*STATED];   // [s(64)|h(512)]
__device__ float g_carryB[BB*STATED];
__device__ float g_zeroc[BB*STATED];    // zero, never written
__device__ float g_y1[BB*FEATD];
__device__ float g_y2[BB*FEATD];
__device__ float g_qmu[TBD*STOCHD];
__device__ float g_qstd[TBD*STOCHD];
__device__ float g_P[TBD*1536];
__device__ float g_PE[TBD*FEATD];
__device__ float g_Wg[512*3*576];
__device__ float g_E[TBD*EMBD];
__device__ float g_praw[TBD*2*STOCHD];
__device__ float g_e0[EMBD];
__device__ float g_e0l1[FEATD];
__device__ double g_acc[3];

__device__ bf16 g_states_bf[TBD*STATED];  // [h|s]
__device__ bf16 g_emb_bf[TBD*EMBD];
__device__ bf16 g_E_bf[TBD*EMBD];
__device__ bf16 g_pcat_bf[TBD*1536];
__device__ bf16 g_big1_bf[TBD*FEATD];
__device__ bf16 g_big2_bf[TBD*FEATD];
__device__ bf16 g_e0_bf[EMBD];
__device__ bf16 g_stW0b[512*1536];
__device__ bf16 g_stW1b[512*512];
__device__ bf16 g_stW2b[128*512];
__device__ bf16 g_epW0b[512*576];
__device__ bf16 g_epW1b[512*512];
__device__ bf16 g_epW2b[1024*512];
__device__ bf16 g_rpW0b[512*576];
__device__ bf16 g_rpW1b[512*512];

// ---------------- math ----------------
__device__ __forceinline__ float softplusf(float x) {
    return fmaxf(x, 0.f) + log1pf(expf(-fabsf(x)));
}
__device__ __forceinline__ float sigmoidf_(float x) { return 1.f / (1.f + expf(-x)); }
__device__ __forceinline__ float eluf(float x) { return x > 0.f ? x : expm1f(x); }
template<int ACT> __device__ __forceinline__ float actf(float v) {
    if (ACT == 1) return eluf(v);
    return v;
}

__device__ __forceinline__ void mma_bf16(float* c, const unsigned* a, const unsigned* b) {
    asm volatile(
        "mma.sync.aligned.m16n8k16.row.col.f32.bf16.bf16.f32 "
        "{%0,%1,%2,%3},{%4,%5,%6,%7},{%8,%9},{%0,%1,%2,%3};"
        : "+f"(c[0]), "+f"(c[1]), "+f"(c[2]), "+f"(c[3])
        : "r"(a[0]), "r"(a[1]), "r"(a[2]), "r"(a[3]), "r"(b[0]), "r"(b[1]));
}

// ---------------- bf16 tensor-core GEMM ----------------
// C[16384,N] = act(A_bf[.,K] @ W_bf[N,K]^T + bias_f32). N%128==0, K%32==0.
template<int ACT, bool ROWSHIFT, bool WF32, bool WBF>
__global__ __launch_bounds__(256, 2) void mma_gemm(
    const bf16* __restrict__ A, int ldA,
    const bf16* __restrict__ W, int ldW,
    const float* __restrict__ bias,
    float* __restrict__ Cf, bf16* __restrict__ Cb, int ldC, int K)
{
    __shared__ __align__(16) unsigned As[2][128 * 20];
    __shared__ __align__(16) unsigned Ws[2][128 * 20];
    int tid = threadIdx.x, lane = tid & 31, wid = tid >> 5;
    int g = lane >> 2, tg = lane & 3;
    int wr = wid >> 2, wc = wid & 3;
    int row0 = blockIdx.y * 128, col0 = blockIdx.x * 128;

    float acc[4][4][4];
#pragma unroll
    for (int mt = 0; mt < 4; mt++)
#pragma unroll
        for (int nt = 0; nt < 4; nt++)
#pragma unroll
            for (int q = 0; q < 4; q++) acc[mt][nt][q] = 0.f;

    const int nc = K / 32;
    uint4 pa[2], pb[2];
#pragma unroll
    for (int i = 0; i < 2; i++) {
        int u = tid + i * 256, row = u >> 2, q = u & 3;
        int grow = row0 + row;
        if (ROWSHIFT && grow >= 256) grow -= 256;
        pa[i] = *reinterpret_cast<const uint4*>(A + (size_t)grow * ldA + q * 8);
        pb[i] = *reinterpret_cast<const uint4*>(W + (size_t)(col0 + row) * ldW + q * 8);
    }
#pragma unroll
    for (int i = 0; i < 2; i++) {
        int u = tid + i * 256, row = u >> 2, q = u & 3;
        *reinterpret_cast<uint4*>(&As[0][row * 20 + q * 4]) = pa[i];
        *reinterpret_cast<uint4*>(&Ws[0][row * 20 + q * 4]) = pb[i];
    }
    __syncthreads();

    int buf = 0;
    for (int c = 0; c < nc; c++) {
        bool nxt = (c + 1 < nc);
        if (nxt) {
            int k0 = (c + 1) * 32;
#pragma unroll
            for (int i = 0; i < 2; i++) {
                int u = tid + i * 256, row = u >> 2, q = u & 3;
                int grow = row0 + row;
                if (ROWSHIFT && grow >= 256) grow -= 256;
                pa[i] = *reinterpret_cast<const uint4*>(A + (size_t)grow * ldA + k0 + q * 8);
                pb[i] = *reinterpret_cast<const uint4*>(W + (size_t)(col0 + row) * ldW + k0 + q * 8);
            }
        }
        const unsigned* as = As[buf];
        const unsigned* ws = Ws[buf];
#pragma unroll
        for (int ks = 0; ks < 2; ks++) {
            unsigned af[4][4], bfr[4][2];
#pragma unroll
            for (int mt = 0; mt < 4; mt++) {
                int r = wr * 64 + mt * 16 + g;
                af[mt][0] = as[r * 20 + ks * 8 + tg];
                af[mt][1] = as[(r + 8) * 20 + ks * 8 + tg];
                af[mt][2] = as[r * 20 + ks * 8 + tg + 4];
                af[mt][3] = as[(r + 8) * 20 + ks * 8 + tg + 4];
            }
#pragma unroll
            for (int nt = 0; nt < 4; nt++) {
                int n = wc * 32 + nt * 8 + g;
                bfr[nt][0] = ws[n * 20 + ks * 8 + tg];
                bfr[nt][1] = ws[n * 20 + ks * 8 + tg + 4];
            }
#pragma unroll
            for (int mt = 0; mt < 4; mt++)
#pragma unroll
                for (int nt = 0; nt < 4; nt++)
                    mma_bf16(acc[mt][nt], af[mt], bfr[nt]);
        }
        if (nxt) {
            int nb = buf ^ 1;
#pragma unroll
            for (int i = 0; i < 2; i++) {
                int u = tid + i * 256, row = u >> 2, q = u & 3;
                *reinterpret_cast<uint4*>(&As[nb][row * 20 + q * 4]) = pa[i];
                *reinterpret_cast<uint4*>(&Ws[nb][row * 20 + q * 4]) = pb[i];
            }
        }
        __syncthreads();
        buf ^= 1;
    }

#pragma unroll
    for (int mt = 0; mt < 4; mt++) {
        int r = row0 + wr * 64 + mt * 16 + g;
#pragma unroll
        for (int nt = 0; nt < 4; nt++) {
            int cc = col0 + wc * 32 + nt * 8 + tg * 2;
            float b0v = bias[cc], b1v = bias[cc + 1];
            float v00 = actf<ACT>(acc[mt][nt][0] + b0v);
            float v01 = actf<ACT>(acc[mt][nt][1] + b1v);
            float v10 = actf<ACT>(acc[mt][nt][2] + b0v);
            float v11 = actf<ACT>(acc[mt][nt][3] + b1v);
            if (WF32) {
                Cf[(size_t)r * ldC + cc]           = v00;
                Cf[(size_t)r * ldC + cc + 1]       = v01;
                Cf[(size_t)(r + 8) * ldC + cc]     = v10;
                Cf[(size_t)(r + 8) * ldC + cc + 1] = v11;
            }
            if (WBF) {
                Cb[(size_t)r * ldC + cc]           = __float2bfloat16(v00);
                Cb[(size_t)r * ldC + cc + 1]       = __float2bfloat16(v01);
                Cb[(size_t)(r + 8) * ldC + cc]     = __float2bfloat16(v10);
                Cb[(size_t)(r + 8) * ldC + cc + 1] = __float2bfloat16(v11);
            }
        }
    }
}

// ---------------- prep ----------------
__global__ void cvt_bf_k(const float* __restrict__ s, bf16* __restrict__ d, long n) {
    for (long i = blockIdx.x * (long)blockDim.x + threadIdx.x; i < n;
         i += (long)gridDim.x * blockDim.x)
        d[i] = __float2bfloat16(s[i]);
}

__global__ void prep_P(const float* __restrict__ action, const float* __restrict__ Wih,
                       const float* __restrict__ bih, const float* __restrict__ bhh,
                       float* __restrict__ P)
{
    int r = blockIdx.x;
    __shared__ float a[ADIM];
    if (threadIdx.x < ADIM) a[threadIdx.x] = action[(size_t)r * ADIM + threadIdx.x];
    __syncthreads();
    for (int j = threadIdx.x; j < 1536; j += 256) {
        float v = bih[j];
#pragma unroll
        for (int k = 0; k < ADIM; k++) v = fmaf(a[k], Wih[j * 70 + 64 + k], v);
        if (j < 1024) v += bhh[j];
        P[(size_t)r * 1536 + j] = v;
    }
}

// Wg[col][gate][k]: k<64 -> Wih[gate*512+col][k], else Whh[gate*512+col][k-64]
__global__ void prep_Wg(const float* __restrict__ Wih, const float* __restrict__ Whh,
                        float* __restrict__ Wg)
{
    long total = 512L * 3 * 576;
    for (long idx = blockIdx.x * (long)blockDim.x + threadIdx.x; idx < total;
         idx += (long)gridDim.x * blockDim.x) {
        int col = (int)(idx / 1728);
        int rem = (int)(idx % 1728);
        int gate = rem / 576, k = rem % 576;
        int wrow = gate * 512 + col;
        Wg[idx] = (k < 64) ? Wih[(size_t)wrow * 70 + k] : Whh[(size_t)wrow * 512 + (k - 64)];
    }
}

// ---------------- sequential step kernels (f32 exact) ----------------
__global__ __launch_bounds__(256) void step_gru(
    const float* __restrict__ cin, const float* __restrict__ Wg,
    const float* __restrict__ P_t, const float* __restrict__ bhh,
    float* __restrict__ cout, bf16* __restrict__ stbf_t)
{
    __shared__ float Xs[32][17];
    __shared__ float Wsm[32][49];
    int tid = threadIdx.x, tx = tid & 31, ty = tid >> 5;
    int r0 = blockIdx.y * 32, c0 = blockIdx.x * 32;
    float accR[4] = {0,0,0,0}, accZ[4] = {0,0,0,0};
    float accNs[4] = {0,0,0,0}, accNh[4] = {0,0,0,0};

    for (int k0 = 0; k0 < STATED; k0 += 16) {
#pragma unroll
        for (int i = 0; i < 2; i++) {
            int e = tid + i * 256, row = e >> 4, kk = e & 15;
            Xs[row][kk] = cin[(size_t)(r0 + row) * STATED + k0 + kk];
        }
#pragma unroll
        for (int i = 0; i < 6; i++) {
            int e = tid + i * 256, col = e / 48, j = e % 48;
            Wsm[col][j] = Wg[(size_t)(c0 + col) * 1728 + (j >> 4) * 576 + k0 + (j & 15)];
        }
        __syncthreads();
        if (k0 < 64) {
#pragma unroll
            for (int kk = 0; kk < 16; kk++) {
                float wr = Wsm[tx][kk], wz = Wsm[tx][16 + kk], wn = Wsm[tx][32 + kk];
#pragma unroll
                for (int i = 0; i < 4; i++) {
                    float a = Xs[ty + 8 * i][kk];
                    accR[i]  = fmaf(a, wr, accR[i]);
                    accZ[i]  = fmaf(a, wz, accZ[i]);
                    accNs[i] = fmaf(a, wn, accNs[i]);
                }
            }
        } else {
#pragma unroll
            for (int kk = 0; kk < 16; kk++) {
                float wr = Wsm[tx][kk], wz = Wsm[tx][16 + kk], wn = Wsm[tx][32 + kk];
#pragma unroll
                for (int i = 0; i < 4; i++) {
                    float a = Xs[ty + 8 * i][kk];
                    accR[i]  = fmaf(a, wr, accR[i]);
                    accZ[i]  = fmaf(a, wz, accZ[i]);
                    accNh[i] = fmaf(a, wn, accNh[i]);
                }
            }
        }
        __syncthreads();
    }
#pragma unroll
    for (int i = 0; i < 4; i++) {
        int gr = r0 + ty + 8 * i, gc = c0 + tx;
        float r = sigmoidf_(accR[i] + P_t[(size_t)gr * 1536 + gc]);
        float z = sigmoidf_(accZ[i] + P_t[(size_t)gr * 1536 + 512 + gc]);
        float hn = accNh[i] + bhh[1024 + gc];
        float n = tanhf(accNs[i] + P_t[(size_t)gr * 1536 + 1024 + gc] + r * hn);
        float hp = cin[(size_t)gr * STATED + 64 + gc];
        float h = (1.f - z) * n + z * hp;
        cout[(size_t)gr * STATED + 64 + gc] = h;
        stbf_t[(size_t)gr * STATED + gc] = __float2bfloat16(h);
    }
}

template<int ACT>
__global__ __launch_bounds__(256) void step_lin(
    const float* __restrict__ X, int ldX,
    const float* __restrict__ W, int ldW,
    const float* __restrict__ Add, int ldAdd,
    float* __restrict__ Y, int ldY, int K)
{
    __shared__ float Xs[32][17];
    __shared__ float Wsm[32][17];
    int tid = threadIdx.x, tx = tid & 31, ty = tid >> 5;
    int r0 = blockIdx.y * 32, c0 = blockIdx.x * 32;
    float acc[4] = {0,0,0,0};
    for (int k0 = 0; k0 < K; k0 += 16) {
#pragma unroll
        for (int i = 0; i < 2; i++) {
            int e = tid + i * 256, row = e >> 4, kk = e & 15;
            Xs[row][kk]  = X[(size_t)(r0 + row) * ldX + k0 + kk];
            Wsm[row][kk] = W[(size_t)(c0 + row) * ldW + k0 + kk];
        }
        __syncthreads();
#pragma unroll
        for (int kk = 0; kk < 16; kk++) {
            float w = Wsm[tx][kk];
#pragma unroll
            for (int i = 0; i < 4; i++)
                acc[i] = fmaf(Xs[ty + 8 * i][kk], w, acc[i]);
        }
        __syncthreads();
    }
#pragma unroll
    for (int i = 0; i < 4; i++) {
        int gr = r0 + ty + 8 * i, gc = c0 + tx;
        Y[(size_t)gr * ldY + gc] = actf<ACT>(acc[i] + Add[(size_t)gr * ldAdd + gc]);
    }
}

__global__ __launch_bounds__(256) void step_l2s(
    const float* __restrict__ y2, const float* __restrict__ W2, const float* __restrict__ b2,
    const float* __restrict__ eps_t, float* __restrict__ qmu_t, float* __restrict__ qstd_t,
    float* __restrict__ cout, bf16* __restrict__ stbf_t)
{
    __shared__ float Xs[16][17];
    __shared__ float Wm[32][17];
    __shared__ float Wsd[32][17];
    int tid = threadIdx.x, tx = tid & 31, ty = tid >> 5;
    int r0 = blockIdx.y * 16, c0 = blockIdx.x * 32;
    float accM[2] = {0,0}, accS[2] = {0,0};
    for (int k0 = 0; k0 < 512; k0 += 16) {
        { int row = tid >> 4, kk = tid & 15;
          Xs[row][kk] = y2[(size_t)(r0 + row) * 512 + k0 + kk]; }
#pragma unroll
        for (int i = 0; i < 2; i++) {
            int e = tid + i * 256, col = e >> 4, kk = e & 15;
            Wm[col][kk]  = W2[(size_t)(c0 + col) * 512 + k0 + kk];
            Wsd[col][kk] = W2[(size_t)(64 + c0 + col) * 512 + k0 + kk];
        }
        __syncthreads();
#pragma unroll
        for (int kk = 0; kk < 16; kk++) {
            float wm = Wm[tx][kk], ws = Wsd[tx][kk];
#pragma unroll
            for (int i = 0; i < 2; i++) {
                float a = Xs[ty + 8 * i][kk];
                accM[i] = fmaf(a, wm, accM[i]);
                accS[i] = fmaf(a, ws, accS[i]);
            }
        }
        __syncthreads();
    }
#pragma unroll
    for (int i = 0; i < 2; i++) {
        int gr = r0 + ty + 8 * i, gc = c0 + tx;
        float mu = accM[i] + b2[gc];
        float sd = softplusf(accS[i] + b2[64 + gc]) + 1e-4f;
        float s = fmaf(sd, eps_t[(size_t)gr * 64 + gc], mu);
        qmu_t[(size_t)gr * 64 + gc] = mu;
        qstd_t[(size_t)gr * 64 + gc] = sd;
        cout[(size_t)gr * STATED + gc] = s;
        stbf_t[(size_t)gr * STATED + 512 + gc] = __float2bfloat16(s);
    }
}

// ---------------- misc ----------------
__global__ void e0_l1(const float* __restrict__ ep_b0, const float* __restrict__ ep_W1,
                      const float* __restrict__ ep_b1, float* __restrict__ l1)
{
    __shared__ float x0[512];
    for (int k = threadIdx.x; k < 512; k += 256) x0[k] = eluf(ep_b0[k]);
    __syncthreads();
    for (int o = threadIdx.x; o < 512; o += 256) {
        float v = ep_b1[o];
        for (int k = 0; k < 512; k++) v = fmaf(x0[k], ep_W1[(size_t)o * 512 + k], v);
        l1[o] = eluf(v);
    }
}

__global__ void e0_head(const float* __restrict__ l1, const float* __restrict__ ep_W2,
                        const float* __restrict__ ep_b2, float* __restrict__ e0)
{
    int o = blockIdx.x * 256 + threadIdx.x;
    float v = ep_b2[o];
    for (int k = 0; k < 512; k++) v = fmaf(l1[k], ep_W2[(size_t)o * 512 + k], v);
    e0[o] = v;
}

__global__ void build_pcat(const bf16* __restrict__ stbf, const bf16* __restrict__ Ebf,
                           const bf16* __restrict__ e0bf, bf16* __restrict__ out)
{
    int r = blockIdx.x;
    const bf16* src = (r < 256) ? e0bf : (Ebf + (size_t)(r - 256) * EMBD);
    bf16* o = out + (size_t)r * 1536;
    const bf16* st = stbf + (size_t)r * STATED;
    for (int c = threadIdx.x; c < 1536; c += 256)
        o[c] = (c < 512) ? st[c] : src[c - 512];
}

// ---------------- reductions ----------------
__global__ void zero_acc_k(double* acc) { if (threadIdx.x < 3) acc[threadIdx.x] = 0.0; }

__global__ void kl_reduce_k(const float* __restrict__ praw, const float* __restrict__ qmu,
                            const float* __restrict__ qstd, double* __restrict__ acc)
{
    __shared__ double sh[256];
    double s = 0.0;
    long total = (long)TBD * STOCHD;
    for (long idx = blockIdx.x * (long)blockDim.x + threadIdx.x; idx < total;
         idx += (long)gridDim.x * blockDim.x) {
        int r = (int)(idx >> 6), i = (int)(idx & 63);
        float pmu = praw[(size_t)r * 128 + i];
        float psd = softplusf(praw[(size_t)r * 128 + 64 + i]) + 1e-4f;
        float qm = qmu[idx], qs = qstd[idx];
        float d = qm - pmu;
        s += (double)(logf(psd / qs) + (qs * qs + d * d) / (2.f * psd * psd) - 0.5f);
    }
    sh[threadIdx.x] = s; __syncthreads();
    for (int o = 128; o > 0; o >>= 1) {
        if (threadIdx.x < o) sh[threadIdx.x] += sh[threadIdx.x + o];
        __syncthreads();
    }
    if (threadIdx.x == 0) atomicAdd(acc, sh[0]);
}

__global__ void emb_reduce_k(const float* __restrict__ emb, const float* __restrict__ embmu,
                             double* __restrict__ acc)
{
    __shared__ double sh[256];
    double s = 0.0;
    long total = (long)TBD * EMBD;
    for (long idx = blockIdx.x * (long)blockDim.x + threadIdx.x; idx < total;
         idx += (long)gridDim.x * blockDim.x) {
        float d = emb[idx] - embmu[idx];
        s += (double)(0.5f * d * d + 0.5f * LOG2PI_F);
    }
    sh[threadIdx.x] = s; __syncthreads();
    for (int o = 128; o > 0; o >>= 1) {
        if (threadIdx.x < o) sh[threadIdx.x] += sh[threadIdx.x + o];
        __syncthreads();
    }
    if (threadIdx.x == 0) atomicAdd(acc, sh[0]);
}

__global__ void reward_reduce_k(const bf16* __restrict__ big2, const float* __restrict__ W,
                                const float* __restrict__ bias, const float* __restrict__ reward,
                                double* __restrict__ acc)
{
    __shared__ double sh[8];
    int lane = threadIdx.x & 31, wib = threadIdx.x >> 5;
    int gwarp = (blockIdx.x * blockDim.x + threadIdx.x) >> 5;
    int nwarps = (gridDim.x * blockDim.x) >> 5;
    double local = 0.0;
    for (int r = gwarp; r < TBD; r += nwarps) {
        float sum = 0.f;
        const bf16* row = big2 + (size_t)r * FEATD;
        for (int k = lane; k < FEATD; k += 32)
            sum = fmaf(__bfloat162float(row[k]), W[k], sum);
#pragma unroll
        for (int o = 16; o > 0; o >>= 1) sum += __shfl_xor_sync(0xffffffffu, sum, o);
        if (lane == 0) {
            float d = reward[r] - (sum + bias[0]);
            local += (double)(0.5f * d * d + 0.5f * LOG2PI_F);
        }
    }
    if (lane == 0) sh[wib] = local;
    __syncthreads();
    if (threadIdx.x == 0) {
        double t = 0.0;
        for (int i = 0; i < 8; i++) t += sh[i];
        atomicAdd(acc, t);
    }
}

__global__ void finalize_k(const double* __restrict__ acc, float* __restrict__ out, int n) {
    double inv = 1.0 / (double)(TT * BB);
    float loss = (float)((acc[0] + acc[1] + acc[2]) * inv);
    for (int i = 0; i < n; i++) out[i] = loss;
}

// ---------------- host ----------------
static void* symaddr(const void* sym) {
    void* p = nullptr;
    cudaGetSymbolAddress(&p, sym);
    return p;
}

extern "C" void kernel_launch(void* const* d_in, const int* in_sizes, int n_in,
                              void* d_out, int out_size)
{
    const float* emb     = (const float*)d_in[0];
    const float* action  = (const float*)d_in[1];
    const float* reward  = (const float*)d_in[2];
    const float* eps     = (const float*)d_in[3];
    const float* gru_Wih = (const float*)d_in[4];
    const float* gru_bih = (const float*)d_in[5];
    const float* gru_Whh = (const float*)d_in[6];
    const float* gru_bhh = (const float*)d_in[7];
    const float* st_W0 = (const float*)d_in[8];  const float* st_b0 = (const float*)d_in[9];
    const float* st_W1 = (const float*)d_in[10]; const float* st_b1 = (const float*)d_in[11];
    const float* st_W2 = (const float*)d_in[12]; const float* st_b2 = (const float*)d_in[13];
    const float* ep_W0 = (const float*)d_in[14]; const float* ep_b0 = (const float*)d_in[15];
    const float* ep_W1 = (const float*)d_in[16]; const float* ep_b1 = (const float*)d_in[17];
    const float* ep_W2 = (const float*)d_in[18]; const float* ep_b2 = (const float*)d_in[19];
    const float* rp_W0 = (const float*)d_in[20]; const float* rp_b0 = (const float*)d_in[21];
    const float* rp_W1 = (const float*)d_in[22]; const float* rp_b1 = (const float*)d_in[23];
    const float* rp_W2 = (const float*)d_in[24]; const float* rp_b2 = (const float*)d_in[25];

    float* carryA = (float*)symaddr(g_carryA);
    float* carryB = (float*)symaddr(g_carryB);
    float* zeroc  = (float*)symaddr(g_zeroc);
    float* y1     = (float*)symaddr(g_y1);
    float* y2     = (float*)symaddr(g_y2);
    float* qmu    = (float*)symaddr(g_qmu);
    float* qstd   = (float*)symaddr(g_qstd);
    float* P      = (float*)symaddr(g_P);
    float* PE     = (float*)symaddr(g_PE);
    float* Wg     = (float*)symaddr(g_Wg);
    float* E      = (float*)symaddr(g_E);
    float* praw   = (float*)symaddr(g_praw);
    float* e0     = (float*)symaddr(g_e0);
    float* e0l1   = (float*)symaddr(g_e0l1);
    double* acc   = (double*)symaddr(g_acc);
    bf16* stbf   = (bf16*)symaddr(g_states_bf);
    bf16* embbf  = (bf16*)symaddr(g_emb_bf);
    bf16* Ebf    = (bf16*)symaddr(g_E_bf);
    bf16* pcatbf = (bf16*)symaddr(g_pcat_bf);
    bf16* big1bf = (bf16*)symaddr(g_big1_bf);
    bf16* big2bf = (bf16*)symaddr(g_big2_bf);
    bf16* e0bf   = (bf16*)symaddr(g_e0_bf);
    bf16* stW0b  = (bf16*)symaddr(g_stW0b);
    bf16* stW1b  = (bf16*)symaddr(g_stW1b);
    bf16* stW2b  = (bf16*)symaddr(g_stW2b);
    bf16* epW0b  = (bf16*)symaddr(g_epW0b);
    bf16* epW1b  = (bf16*)symaddr(g_epW1b);
    bf16* epW2b  = (bf16*)symaddr(g_epW2b);
    bf16* rpW0b  = (bf16*)symaddr(g_rpW0b);
    bf16* rpW1b  = (bf16*)symaddr(g_rpW1b);

    zero_acc_k<<<1, 32>>>(acc);

    // conversions + prep
    cvt_bf_k<<<2048, 256>>>(emb,   embbf, (long)TBD * EMBD);
    cvt_bf_k<<<512, 256>>>(st_W0, stW0b, 512L * 1536);
    cvt_bf_k<<<256, 256>>>(st_W1, stW1b, 512L * 512);
    cvt_bf_k<<<64,  256>>>(st_W2, stW2b, 128L * 512);
    cvt_bf_k<<<256, 256>>>(ep_W0, epW0b, 512L * 576);
    cvt_bf_k<<<256, 256>>>(ep_W1, epW1b, 512L * 512);
    cvt_bf_k<<<512, 256>>>(ep_W2, epW2b, 1024L * 512);
    cvt_bf_k<<<256, 256>>>(rp_W0, rpW0b, 512L * 576);
    cvt_bf_k<<<256, 256>>>(rp_W1, rpW1b, 512L * 512);
    prep_P<<<TBD, 256>>>(action, gru_Wih, gru_bih, gru_bhh, P);
    prep_Wg<<<1024, 256>>>(gru_Wih, gru_Whh, Wg);
    e0_l1<<<1, 256>>>(ep_b0, ep_W1, ep_b1, e0l1);
    e0_head<<<4, 256>>>(e0l1, ep_W2, ep_b2, e0);
    cvt_bf_k<<<4, 256>>>(e0, e0bf, EMBD);

    // PE = emb_prev @ st_W0[:,512:1536]^T + st_b0   (tensor core, rowShift)
    mma_gemm<0, true, true, false><<<dim3(4, 128), 256>>>(
        embbf, EMBD, stW0b + 512, 1536, st_b0, PE, nullptr, FEATD, EMBD);

    // sequential recurrence (exact f32)
    for (int t = 0; t < TT; t++) {
        float* cin  = (t == 0) ? zeroc : ((t & 1) ? carryB : carryA);
        float* cout = ((t + 1) & 1) ? carryB : carryA;
        bf16* st_t  = stbf + (size_t)t * BB * STATED;
        step_gru<<<dim3(16, 8), 256>>>(cin, Wg, P + (size_t)t * BB * 1536, gru_bhh, cout, st_t);
        step_lin<1><<<dim3(16, 8), 256>>>(cout + 64, STATED, st_W0, 1536,
                                          PE + (size_t)t * BB * FEATD, FEATD, y1, FEATD, HIDD);
        step_lin<1><<<dim3(16, 8), 256>>>(y1, FEATD, st_W1, FEATD, st_b1, 0, y2, FEATD, FEATD);
        step_l2s<<<dim3(2, 16), 256>>>(y2, st_W2, st_b2, eps + (size_t)t * BB * STOCHD,
                                       qmu + (size_t)t * BB * STOCHD,
                                       qstd + (size_t)t * BB * STOCHD, cout, st_t);
    }

    // shared ep-MLP: E = ep_mlp(states) = emb_mu; row-shifted = pre_emb
    mma_gemm<1, false, false, true><<<dim3(4, 128), 256>>>(
        stbf, STATED, epW0b, STATED, ep_b0, nullptr, big1bf, FEATD, STATED);
    mma_gemm<1, false, false, true><<<dim3(4, 128), 256>>>(
        big1bf, FEATD, epW1b, FEATD, ep_b1, nullptr, big2bf, FEATD, FEATD);
    mma_gemm<0, false, true, true><<<dim3(8, 128), 256>>>(
        big2bf, FEATD, epW2b, FEATD, ep_b2, E, Ebf, EMBD, FEATD);

    // prior path
    build_pcat<<<TBD, 256>>>(stbf, Ebf, e0bf, pcatbf);
    mma_gemm<1, false, false, true><<<dim3(4, 128), 256>>>(
        pcatbf, 1536, stW0b, 1536, st_b0, nullptr, big1bf, FEATD, 1536);
    mma_gemm<1, false, false, true><<<dim3(4, 128), 256>>>(
        big1bf, FEATD, stW1b, FEATD, st_b1, nullptr, big2bf, FEATD, FEATD);
    mma_gemm<0, false, true, false><<<dim3(1, 128), 256>>>(
        big2bf, FEATD, stW2b, FEATD, st_b2, praw, nullptr, 128, FEATD);
    kl_reduce_k<<<1024, 256>>>(praw, qmu, qstd, acc + 0);

    // emb loss
    emb_reduce_k<<<2048, 256>>>(emb, E, acc + 1);

    // reward loss
    mma_gemm<1, false, false, true><<<dim3(4, 128), 256>>>(
        stbf, STATED, rpW0b, STATED, rp_b0, nullptr, big1bf, FEATD, STATED);
    mma_gemm<1, false, false, true><<<dim3(4, 128), 256>>>(
        big1bf, FEATD, rpW1b, FEATD, rp_b1, nullptr, big2bf, FEATD, FEATD);
    reward_reduce_k<<<512, 256>>>(big2bf, rp_W2, rp_b2, reward, acc + 2);

    finalize_k<<<1, 1>>>(acc, (float*)d_out, out_size);
}